// round 1
// baseline (speedup 1.0000x reference)
#include <cuda_runtime.h>
#include <cuda_bf16.h>

// ---------------------------------------------------------------------------
// Attention_11519102287955 : B=8, N=1024, C=768, H=12, D=64
//   qkv = x @ w_qkv + b_qkv            (8192 x 768) x (768 x 2304)
//   per (b,h): S = Q K^T * temp[h], diag -> -inf, softmax, O = S V
//   out = AO @ w_proj + b_proj         (8192 x 768) x (768 x 768)
// fp32 SIMT with packed f32x2 FMA (sm_103a FFMA2 pipe).
// ---------------------------------------------------------------------------

typedef unsigned long long u64;

#define BATCH 8
#define NSEQ  1024
#define CDIM  768
#define NH    12
#define HD    64
#define MROWS (BATCH * NSEQ)   // 8192

// scratch (device globals; allocation in kernel_launch is forbidden)
__device__ float g_Q[BATCH * NH * NSEQ * HD];
__device__ float g_K[BATCH * NH * NSEQ * HD];
__device__ float g_V[BATCH * NH * NSEQ * HD];
__device__ float g_AO[MROWS * CDIM];

// ---- packed f32x2 helpers --------------------------------------------------
__device__ __forceinline__ u64 pk2(float x, float y) {
    u64 r; asm("mov.b64 %0, {%1, %2};" : "=l"(r) : "f"(x), "f"(y)); return r;
}
__device__ __forceinline__ void upk2(u64 v, float& x, float& y) {
    asm("mov.b64 {%0, %1}, %2;" : "=f"(x), "=f"(y) : "l"(v));
}
__device__ __forceinline__ u64 ffma2(u64 a, u64 b, u64 c) {
    u64 d; asm("fma.rn.f32x2 %0, %1, %2, %3;" : "=l"(d) : "l"(a), "l"(b), "l"(c));
    return d;
}
__device__ __forceinline__ u64 fmul2(u64 a, u64 b) {
    u64 d; asm("mul.rn.f32x2 %0, %1, %2;" : "=l"(d) : "l"(a), "l"(b));
    return d;
}

// ---------------------------------------------------------------------------
// GEMM: C[M,Ncol] = A[M,K] @ Bw[K,Ncol] + bias
// 128x128 block tile, K-tile 16, 256 threads, 8x8 per-thread microtile.
// MODE 1: A = x, epilogue scatters into g_Q/g_K/g_V (B,H,N,D) layout.
// MODE 2: A = g_AO (internal), plain epilogue into Cout.
// ---------------------------------------------------------------------------
#define GBM 128
#define GBN 128
#define GBK 16
#define GPITCH (GBM + 4)   // 132 floats

template <int MODE>
__global__ void __launch_bounds__(256) gemm_kernel(
    const float* __restrict__ Ain, const float* __restrict__ Bw,
    const float* __restrict__ bias, float* __restrict__ Cout,
    int Kdim, int Ncol)
{
    __shared__ float As[GBK * GPITCH];   // As[k][m]  (transposed)
    __shared__ float Bs[GBK * GPITCH];   // Bs[k][n]

    const float* A = (MODE == 2) ? (const float*)g_AO : Ain;

    const int tid = threadIdx.x;
    const int ty = tid >> 4;        // 0..15 -> row group
    const int tx = tid & 15;        // 0..15 -> col group
    const int bm = blockIdx.y * GBM;
    const int bn = blockIdx.x * GBN;

    u64 acc[8][4];
#pragma unroll
    for (int i = 0; i < 8; i++)
#pragma unroll
        for (int j = 0; j < 4; j++) acc[i][j] = 0ull;

    for (int kt = 0; kt < Kdim; kt += GBK) {
        // A tile: 128 rows x 16 k, store transposed As[k][m]
#pragma unroll
        for (int it = 0; it < 2; it++) {
            int lin = tid + it * 256;            // 0..511
            int row = lin >> 2;
            int c4  = (lin & 3) << 2;
            float4 av = *(const float4*)&A[(size_t)(bm + row) * Kdim + kt + c4];
            As[(c4 + 0) * GPITCH + row] = av.x;
            As[(c4 + 1) * GPITCH + row] = av.y;
            As[(c4 + 2) * GPITCH + row] = av.z;
            As[(c4 + 3) * GPITCH + row] = av.w;
        }
        // B tile: 16 k x 128 cols, natural layout Bs[k][n]
#pragma unroll
        for (int it = 0; it < 2; it++) {
            int lin = tid + it * 256;
            int kr = lin >> 5;
            int c4 = (lin & 31) << 2;
            *(float4*)&Bs[kr * GPITCH + c4] =
                *(const float4*)&Bw[(size_t)(kt + kr) * Ncol + bn + c4];
        }
        __syncthreads();

#pragma unroll
        for (int k = 0; k < GBK; k++) {
            float4 a0 = *(const float4*)&As[k * GPITCH + ty * 8];
            float4 a1 = *(const float4*)&As[k * GPITCH + ty * 8 + 4];
            ulonglong2 b0 = *(const ulonglong2*)&Bs[k * GPITCH + tx * 8];
            ulonglong2 b1 = *(const ulonglong2*)&Bs[k * GPITCH + tx * 8 + 4];
            float av[8] = {a0.x, a0.y, a0.z, a0.w, a1.x, a1.y, a1.z, a1.w};
            u64 bq[4] = {b0.x, b0.y, b1.x, b1.y};
#pragma unroll
            for (int i = 0; i < 8; i++) {
                u64 ad = pk2(av[i], av[i]);
#pragma unroll
                for (int j = 0; j < 4; j++)
                    acc[i][j] = ffma2(ad, bq[j], acc[i][j]);
            }
        }
        __syncthreads();
    }

    // epilogue
#pragma unroll
    for (int i = 0; i < 8; i++) {
        int m = bm + ty * 8 + i;
#pragma unroll
        for (int j = 0; j < 4; j++) {
            float x0, x1;
            upk2(acc[i][j], x0, x1);
            int col = bn + tx * 8 + j * 2;
            x0 += bias[col];
            x1 += bias[col + 1];
            if (MODE == 1) {
                // qkv scatter: col -> (s, h, d); m -> (b, n)
                int bb = m >> 10, nn = m & 1023;
                int s  = col / CDIM;
                int hh = (col % CDIM) >> 6;
                int dd = col & 63;
                float* dst = (s == 0) ? g_Q : (s == 1) ? g_K : g_V;
                size_t off = ((((size_t)bb * NH + hh) << 10) + nn) * HD + dd;
                dst[off]     = x0;
                dst[off + 1] = x1;
            } else {
                float2 o = make_float2(x0, x1);
                *(float2*)&Cout[(size_t)m * Ncol + col] = o;
            }
        }
    }
}

// ---------------------------------------------------------------------------
// Flash attention (fp32, diag-masked, per-head temperature)
// Block: 128 q-rows of one (b,h); 256 threads as 16x16.
// Thread (ty,tx): 8 q-rows (ty*8..+8), score cols tx*4..+4, out d tx*4..+4.
// smem: Qs[d][r] 64x132 (q pre-scaled by temp), Ks[d][c] 64x68,
//       Vs[c][d] 64x68, Ps[r][c] 128x68   -> 103,424 bytes dynamic.
// ---------------------------------------------------------------------------
#define Q_PITCH 132
#define K_PITCH 68
#define ATTN_SMEM_FLOATS (64 * Q_PITCH + 64 * K_PITCH + 64 * K_PITCH + 128 * K_PITCH)
#define ATTN_SMEM_BYTES  (ATTN_SMEM_FLOATS * 4)

__global__ void __launch_bounds__(256, 1) attn_kernel(const float* __restrict__ temp)
{
    extern __shared__ float sm[];
    float* Qs = sm;                                   // [64][132]
    float* Ks = sm + 64 * Q_PITCH;                    // [64][68]
    float* Vs = Ks + 64 * K_PITCH;                    // [64][68]
    float* Ps = Vs + 64 * K_PITCH;                    // [128][68]

    const int tid = threadIdx.x;
    const int ty = tid >> 4;
    const int tx = tid & 15;
    const int bh = blockIdx.y;            // 0..95
    const int q0 = blockIdx.x * 128;

    const float* Qg = g_Q + (size_t)bh * NSEQ * HD;
    const float* Kg = g_K + (size_t)bh * NSEQ * HD;
    const float* Vg = g_V + (size_t)bh * NSEQ * HD;
    const float tscale = temp[bh % NH];

    // load Q tile (pre-scaled by temperature), transposed Qs[d][r]
#pragma unroll
    for (int it = 0; it < 8; it++) {
        int lin = tid + it * 256;                 // 0..2047
        int r = lin >> 4;
        int c4 = (lin & 15) << 2;
        float4 v = *(const float4*)&Qg[(size_t)(q0 + r) * HD + c4];
        Qs[(c4 + 0) * Q_PITCH + r] = v.x * tscale;
        Qs[(c4 + 1) * Q_PITCH + r] = v.y * tscale;
        Qs[(c4 + 2) * Q_PITCH + r] = v.z * tscale;
        Qs[(c4 + 3) * Q_PITCH + r] = v.w * tscale;
    }

    u64 Oa[8][2];
    float mrow[8], lrow[8];
#pragma unroll
    for (int i = 0; i < 8; i++) {
        Oa[i][0] = 0ull; Oa[i][1] = 0ull;
        mrow[i] = -1e30f; lrow[i] = 0.0f;
    }

    for (int kt = 0; kt < NSEQ / 64; kt++) {
        const int k0 = kt * 64;
        __syncthreads();   // all PV reads of Ks/Vs from previous tile done
        // load K (transposed Ks[d][c]) and V (natural Vs[c][d])
#pragma unroll
        for (int it = 0; it < 4; it++) {
            int lin = tid + it * 256;            // 0..1023
            int r = lin >> 4;
            int c4 = (lin & 15) << 2;
            float4 kv = *(const float4*)&Kg[(size_t)(k0 + r) * HD + c4];
            Ks[(c4 + 0) * K_PITCH + r] = kv.x;
            Ks[(c4 + 1) * K_PITCH + r] = kv.y;
            Ks[(c4 + 2) * K_PITCH + r] = kv.z;
            Ks[(c4 + 3) * K_PITCH + r] = kv.w;
            float4 vv = *(const float4*)&Vg[(size_t)(k0 + r) * HD + c4];
            *(float4*)&Vs[r * K_PITCH + c4] = vv;
        }
        __syncthreads();

        // ---- scores: S[8][4] = (Q*temp) . K^T ----
        u64 sc[8][2];
#pragma unroll
        for (int i = 0; i < 8; i++) { sc[i][0] = 0ull; sc[i][1] = 0ull; }

#pragma unroll 8
        for (int dd = 0; dd < HD; dd++) {
            ulonglong2 kk = *(const ulonglong2*)&Ks[dd * K_PITCH + tx * 4];
            float4 qa = *(const float4*)&Qs[dd * Q_PITCH + ty * 8];
            float4 qb = *(const float4*)&Qs[dd * Q_PITCH + ty * 8 + 4];
            float qv[8] = {qa.x, qa.y, qa.z, qa.w, qb.x, qb.y, qb.z, qb.w};
#pragma unroll
            for (int i = 0; i < 8; i++) {
                u64 qd = pk2(qv[i], qv[i]);
                sc[i][0] = ffma2(qd, kk.x, sc[i][0]);
                sc[i][1] = ffma2(qd, kk.y, sc[i][1]);
            }
        }

        // ---- online softmax update ----
#pragma unroll
        for (int i = 0; i < 8; i++) {
            float s0, s1, s2, s3;
            upk2(sc[i][0], s0, s1);
            upk2(sc[i][1], s2, s3);
            int qg = q0 + ty * 8 + i;
            int kg = k0 + tx * 4;
            if (qg == kg)     s0 = -1e30f;
            if (qg == kg + 1) s1 = -1e30f;
            if (qg == kg + 2) s2 = -1e30f;
            if (qg == kg + 3) s3 = -1e30f;

            float mx = fmaxf(fmaxf(s0, s1), fmaxf(s2, s3));
            mx = fmaxf(mx, __shfl_xor_sync(0xffffffffu, mx, 1));
            mx = fmaxf(mx, __shfl_xor_sync(0xffffffffu, mx, 2));
            mx = fmaxf(mx, __shfl_xor_sync(0xffffffffu, mx, 4));
            mx = fmaxf(mx, __shfl_xor_sync(0xffffffffu, mx, 8));

            float mnew = fmaxf(mrow[i], mx);
            float corr = __expf(mrow[i] - mnew);
            mrow[i] = mnew;

            float p0 = __expf(s0 - mnew);
            float p1 = __expf(s1 - mnew);
            float p2 = __expf(s2 - mnew);
            float p3 = __expf(s3 - mnew);
            float rs = (p0 + p1) + (p2 + p3);
            rs += __shfl_xor_sync(0xffffffffu, rs, 1);
            rs += __shfl_xor_sync(0xffffffffu, rs, 2);
            rs += __shfl_xor_sync(0xffffffffu, rs, 4);
            rs += __shfl_xor_sync(0xffffffffu, rs, 8);
            lrow[i] = lrow[i] * corr + rs;

            u64 cd = pk2(corr, corr);
            Oa[i][0] = fmul2(Oa[i][0], cd);
            Oa[i][1] = fmul2(Oa[i][1], cd);

            float4 pv = make_float4(p0, p1, p2, p3);
            *(float4*)&Ps[(ty * 8 + i) * K_PITCH + tx * 4] = pv;
        }
        __syncthreads();   // Ps complete before PV reads

        // ---- O += P @ V ----
#pragma unroll 2
        for (int c4 = 0; c4 < 16; c4++) {
            ulonglong2 v0 = *(const ulonglong2*)&Vs[(c4 * 4 + 0) * K_PITCH + tx * 4];
            ulonglong2 v1 = *(const ulonglong2*)&Vs[(c4 * 4 + 1) * K_PITCH + tx * 4];
            ulonglong2 v2 = *(const ulonglong2*)&Vs[(c4 * 4 + 2) * K_PITCH + tx * 4];
            ulonglong2 v3 = *(const ulonglong2*)&Vs[(c4 * 4 + 3) * K_PITCH + tx * 4];
#pragma unroll
            for (int i = 0; i < 8; i++) {
                float4 pv = *(const float4*)&Ps[(ty * 8 + i) * K_PITCH + c4 * 4];
                u64 d0 = pk2(pv.x, pv.x);
                Oa[i][0] = ffma2(d0, v0.x, Oa[i][0]);
                Oa[i][1] = ffma2(d0, v0.y, Oa[i][1]);
                u64 d1 = pk2(pv.y, pv.y);
                Oa[i][0] = ffma2(d1, v1.x, Oa[i][0]);
                Oa[i][1] = ffma2(d1, v1.y, Oa[i][1]);
                u64 d2 = pk2(pv.z, pv.z);
                Oa[i][0] = ffma2(d2, v2.x, Oa[i][0]);
                Oa[i][1] = ffma2(d2, v2.y, Oa[i][1]);
                u64 d3 = pk2(pv.w, pv.w);
                Oa[i][0] = ffma2(d3, v3.x, Oa[i][0]);
                Oa[i][1] = ffma2(d3, v3.y, Oa[i][1]);
            }
        }
    }

    // epilogue: AO in (B,N,H,D) = (B,N,C) layout
    const int b = bh / NH, h = bh % NH;
#pragma unroll
    for (int i = 0; i < 8; i++) {
        float inv = 1.0f / lrow[i];
        float o0, o1, o2, o3;
        upk2(Oa[i][0], o0, o1);
        upk2(Oa[i][1], o2, o3);
        int n = q0 + ty * 8 + i;
        size_t off = ((size_t)(b * NSEQ + n)) * CDIM + h * HD + tx * 4;
        float4 ov = make_float4(o0 * inv, o1 * inv, o2 * inv, o3 * inv);
        *(float4*)&g_AO[off] = ov;
    }
}

// ---------------------------------------------------------------------------
extern "C" void kernel_launch(void* const* d_in, const int* in_sizes, int n_in,
                              void* d_out, int out_size)
{
    (void)in_sizes; (void)n_in; (void)out_size;
    const float* x      = (const float*)d_in[0];
    const float* w_qkv  = (const float*)d_in[1];
    const float* b_qkv  = (const float*)d_in[2];
    const float* w_proj = (const float*)d_in[3];
    const float* b_proj = (const float*)d_in[4];
    const float* temp   = (const float*)d_in[5];
    float* out = (float*)d_out;

    cudaFuncSetAttribute(attn_kernel,
                         cudaFuncAttributeMaxDynamicSharedMemorySize,
                         ATTN_SMEM_BYTES);

    // 1) QKV GEMM with scatter epilogue
    gemm_kernel<1><<<dim3(3 * CDIM / GBN, MROWS / GBM), 256>>>(
        x, w_qkv, b_qkv, nullptr, CDIM, 3 * CDIM);

    // 2) flash attention over 96 (b,h) pairs, 8 q-blocks each
    attn_kernel<<<dim3(NSEQ / 128, BATCH * NH), 256, ATTN_SMEM_BYTES>>>(temp);

    // 3) output projection
    gemm_kernel<2><<<dim3(CDIM / GBN, MROWS / GBM), 256>>>(
        nullptr, w_proj, b_proj, out, CDIM, CDIM);
}

// round 4
// speedup vs baseline: 1.3728x; 1.3728x over previous
#include <cuda_runtime.h>
#include <cuda_bf16.h>
#include <cstdint>

// ---------------------------------------------------------------------------
// Attention_11519102287955 : B=8, N=1024, C=768, H=12, D=64
// Round 4: round-3 design with the stage-loader fixed (was loading only half
// of each K-chunk -> NaN). GEMMs on mma.sync m16n8k16 bf16 split hi/lo x3.
// Attention fp32 SIMT.
// ---------------------------------------------------------------------------

typedef unsigned long long u64;

#define BATCH 8
#define NSEQ  1024
#define CDIM  768
#define NH    12
#define HD    64
#define MROWS (BATCH * NSEQ)   // 8192

// ---- device-global scratch --------------------------------------------------
__device__ float g_Q[BATCH * NH * NSEQ * HD];
__device__ float g_K[BATCH * NH * NSEQ * HD];
__device__ float g_V[BATCH * NH * NSEQ * HD];
__device__ __nv_bfloat16 g_xh[MROWS * CDIM];
__device__ __nv_bfloat16 g_xl[MROWS * CDIM];
__device__ __nv_bfloat16 g_wqh[3 * CDIM * CDIM];
__device__ __nv_bfloat16 g_wql[3 * CDIM * CDIM];
__device__ __nv_bfloat16 g_wph[CDIM * CDIM];
__device__ __nv_bfloat16 g_wpl[CDIM * CDIM];
__device__ __nv_bfloat16 g_AOh[MROWS * CDIM];
__device__ __nv_bfloat16 g_AOl[MROWS * CDIM];

// ---- helpers ----------------------------------------------------------------
__device__ __forceinline__ uint32_t smem_u32(const void* p) {
    uint32_t a;
    asm("{ .reg .u64 t; cvta.to.shared.u64 t, %1; cvt.u32.u64 %0, t; }"
        : "=r"(a) : "l"(p));
    return a;
}

__device__ __forceinline__ void ldsm_x4(uint32_t& r0, uint32_t& r1,
                                        uint32_t& r2, uint32_t& r3, uint32_t a) {
    asm volatile("ldmatrix.sync.aligned.m8n8.x4.shared.b16 {%0,%1,%2,%3}, [%4];"
                 : "=r"(r0), "=r"(r1), "=r"(r2), "=r"(r3) : "r"(a));
}

__device__ __forceinline__ void mma16816(float* d, const uint32_t* a,
                                         const uint32_t* b) {
    asm volatile(
        "mma.sync.aligned.m16n8k16.row.col.f32.bf16.bf16.f32 "
        "{%0,%1,%2,%3}, {%4,%5,%6,%7}, {%8,%9}, {%0,%1,%2,%3};"
        : "+f"(d[0]), "+f"(d[1]), "+f"(d[2]), "+f"(d[3])
        : "r"(a[0]), "r"(a[1]), "r"(a[2]), "r"(a[3]), "r"(b[0]), "r"(b[1]));
}

#define CP_ASYNC16(s, g) \
    asm volatile("cp.async.cg.shared.global [%0], [%1], 16;" :: "r"(s), "l"(g))
#define CP_COMMIT()   asm volatile("cp.async.commit_group;" ::: "memory")
#define CP_WAIT(n)    asm volatile("cp.async.wait_group %0;" :: "n"(n) : "memory")

// ---- packed f32x2 helpers (attention) ----------------------------------------
__device__ __forceinline__ u64 pk2(float x, float y) {
    u64 r; asm("mov.b64 %0, {%1, %2};" : "=l"(r) : "f"(x), "f"(y)); return r;
}
__device__ __forceinline__ void upk2(u64 v, float& x, float& y) {
    asm("mov.b64 {%0, %1}, %2;" : "=f"(x), "=f"(y) : "l"(v));
}
__device__ __forceinline__ u64 ffma2(u64 a, u64 b, u64 c) {
    u64 d; asm("fma.rn.f32x2 %0, %1, %2, %3;" : "=l"(d) : "l"(a), "l"(b), "l"(c));
    return d;
}
__device__ __forceinline__ u64 fmul2(u64 a, u64 b) {
    u64 d; asm("mul.rn.f32x2 %0, %1, %2;" : "=l"(d) : "l"(a), "l"(b));
    return d;
}

// ---------------------------------------------------------------------------
// split fp32 -> bf16 hi/lo
// ---------------------------------------------------------------------------
__device__ __forceinline__ void split4(const float4 v, uint2& hi, uint2& lo) {
    __nv_bfloat16 h0 = __float2bfloat16(v.x), h1 = __float2bfloat16(v.y);
    __nv_bfloat16 h2 = __float2bfloat16(v.z), h3 = __float2bfloat16(v.w);
    __nv_bfloat16 l0 = __float2bfloat16(v.x - __bfloat162float(h0));
    __nv_bfloat16 l1 = __float2bfloat16(v.y - __bfloat162float(h1));
    __nv_bfloat16 l2 = __float2bfloat16(v.z - __bfloat162float(h2));
    __nv_bfloat16 l3 = __float2bfloat16(v.w - __bfloat162float(h3));
    hi.x = ((uint32_t)__bfloat16_as_ushort(h1) << 16) | __bfloat16_as_ushort(h0);
    hi.y = ((uint32_t)__bfloat16_as_ushort(h3) << 16) | __bfloat16_as_ushort(h2);
    lo.x = ((uint32_t)__bfloat16_as_ushort(l1) << 16) | __bfloat16_as_ushort(l0);
    lo.y = ((uint32_t)__bfloat16_as_ushort(l3) << 16) | __bfloat16_as_ushort(l2);
}

__global__ void __launch_bounds__(256) split_x_kernel(
    const float* __restrict__ x, __nv_bfloat16* __restrict__ xh,
    __nv_bfloat16* __restrict__ xl, int n)
{
    int i = (blockIdx.x * 256 + threadIdx.x) * 4;
    if (i >= n) return;
    float4 v = *(const float4*)(x + i);
    uint2 hi, lo;
    split4(v, hi, lo);
    *(uint2*)(xh + i) = hi;
    *(uint2*)(xl + i) = lo;
}

// transpose + split: wT[n][k] = w[k][n]
__global__ void __launch_bounds__(256) tsplit_w_kernel(
    const float* __restrict__ w, __nv_bfloat16* __restrict__ wTh,
    __nv_bfloat16* __restrict__ wTl, int Kd, int Nc)
{
    int u = blockIdx.x * 256 + threadIdx.x;
    int kq = Kd >> 2;
    if (u >= kq * Nc) return;
    int n = u / kq;
    int k0 = (u - n * kq) * 4;
    float4 v;
    v.x = w[(size_t)(k0 + 0) * Nc + n];
    v.y = w[(size_t)(k0 + 1) * Nc + n];
    v.z = w[(size_t)(k0 + 2) * Nc + n];
    v.w = w[(size_t)(k0 + 3) * Nc + n];
    uint2 hi, lo;
    split4(v, hi, lo);
    *(uint2*)(wTh + (size_t)n * Kd + k0) = hi;
    *(uint2*)(wTl + (size_t)n * Kd + k0) = lo;
}

// ---------------------------------------------------------------------------
// mma.sync GEMM: C[8192, Ncol] = A[8192,768] @ B^T (+bias)
//   A hi/lo [M][768] bf16, B hi/lo [Ncol][768] bf16 (K-major).
// 128m x 128n CTA tile, 8 warps (64m x 32n each), Kc=32, 2-stage cp.async.
// MODE 1: scatter into g_Q/g_K/g_V fp32. MODE 2: fp32 out.
// ---------------------------------------------------------------------------
#define KC 32
#define NCH (CDIM / KC)          // 24
#define PITCH 40                 // bf16 elems per smem row (80 B, conflict-free)
#define MAT_BYTES (128 * PITCH * 2)       // 10240
#define STG_BYTES (4 * MAT_BYTES)         // 40960: Ah, Al, Bh, Bl
#define GEMM_SMEM (2 * STG_BYTES)         // 81920

template <int MODE>
__global__ void __launch_bounds__(256, 1) gemm_mma(
    const __nv_bfloat16* __restrict__ Ah_g, const __nv_bfloat16* __restrict__ Al_g,
    const __nv_bfloat16* __restrict__ Bh_g, const __nv_bfloat16* __restrict__ Bl_g,
    const float* __restrict__ bias, float* __restrict__ Cout, int Ncol)
{
    extern __shared__ char smem[];
    const uint32_t sb = smem_u32(smem);

    const int tid = threadIdx.x;
    const int wid = tid >> 5, lane = tid & 31;
    const int wm = wid & 1;          // 2 warps in m
    const int wn = wid >> 1;         // 4 warps in n
    const int bm = blockIdx.y * 128;
    const int bn = blockIdx.x * 128;

    const __nv_bfloat16* gsrc[4] = {Ah_g, Al_g, Bh_g, Bl_g};

    // accumulators: [mtile 4][ntile 4][4]
    float acc[4][4][4];
#pragma unroll
    for (int i = 0; i < 4; i++)
#pragma unroll
        for (int j = 0; j < 4; j++)
#pragma unroll
            for (int r = 0; r < 4; r++) acc[i][j][r] = 0.0f;

    // ---- async stage loader: 4 matrices x 128 rows x 4 16B-chunks (64 B/row)
    auto load_stage = [&](int s, int chunk) {
        const int kt = chunk * KC;
        const char* base = smem + s * STG_BYTES;
#pragma unroll
        for (int it = 0; it < 8; it++) {
            int c = tid + it * 256;          // 0..2047
            int mat = c >> 9;                // 0..3
            int r = (c >> 2) & 127;
            int q = c & 3;                   // 4 x 16B per 64-byte row
            uint32_t saddr = smem_u32(base + mat * MAT_BYTES + r * (PITCH * 2) + q * 16);
            int grow = (mat < 2 ? bm : bn) + r;
            const __nv_bfloat16* g = gsrc[mat] + (size_t)grow * CDIM + kt + q * 8;
            CP_ASYNC16(saddr, g);
        }
    };

    load_stage(0, 0);
    CP_COMMIT();

    for (int i = 0; i < NCH; i++) {
        const int s = i & 1;
        if (i + 1 < NCH) {
            load_stage(s ^ 1, i + 1);
            CP_COMMIT();
            CP_WAIT(1);
        } else {
            CP_WAIT(0);
        }
        __syncthreads();

        const uint32_t ab = sb + s * STG_BYTES;
#pragma unroll
        for (int ks = 0; ks < 2; ks++) {
            // A fragments (4 mtiles, hi/lo)
            uint32_t ah[4][4], al[4][4];
#pragma unroll
            for (int mt = 0; mt < 4; mt++) {
                int row = wm * 64 + mt * 16 + (lane & 15);
                uint32_t off = row * (PITCH * 2) + ks * 32 + (lane >> 4) * 16;
                ldsm_x4(ah[mt][0], ah[mt][1], ah[mt][2], ah[mt][3], ab + off);
                ldsm_x4(al[mt][0], al[mt][1], al[mt][2], al[mt][3],
                        ab + MAT_BYTES + off);
            }
            // B fragments (4 ntiles via 2 x4 loads, hi/lo)
            uint32_t bh[4][2], bl[4][2];
#pragma unroll
            for (int p = 0; p < 2; p++) {
                int row = wn * 32 + p * 16 + (lane & 15);
                uint32_t off = row * (PITCH * 2) + ks * 32 + (lane >> 4) * 16;
                uint32_t r0, r1, r2, r3;
                ldsm_x4(r0, r1, r2, r3, ab + 2 * MAT_BYTES + off);
                bh[p * 2 + 0][0] = r0; bh[p * 2 + 0][1] = r2;
                bh[p * 2 + 1][0] = r1; bh[p * 2 + 1][1] = r3;
                ldsm_x4(r0, r1, r2, r3, ab + 3 * MAT_BYTES + off);
                bl[p * 2 + 0][0] = r0; bl[p * 2 + 0][1] = r2;
                bl[p * 2 + 1][0] = r1; bl[p * 2 + 1][1] = r3;
            }
#pragma unroll
            for (int mt = 0; mt < 4; mt++)
#pragma unroll
                for (int nt = 0; nt < 4; nt++) {
                    mma16816(acc[mt][nt], ah[mt], bh[nt]);
                    mma16816(acc[mt][nt], ah[mt], bl[nt]);
                    mma16816(acc[mt][nt], al[mt], bh[nt]);
                }
        }
        __syncthreads();
    }

    // ---- epilogue ----
#pragma unroll
    for (int mt = 0; mt < 4; mt++) {
#pragma unroll
        for (int nt = 0; nt < 4; nt++) {
            int row0 = bm + wm * 64 + mt * 16 + (lane >> 2);
            int col0 = bn + wn * 32 + nt * 8 + 2 * (lane & 3);
            float b0 = bias[col0], b1 = bias[col0 + 1];
            float2 v0 = make_float2(acc[mt][nt][0] + b0, acc[mt][nt][1] + b1);
            float2 v1 = make_float2(acc[mt][nt][2] + b0, acc[mt][nt][3] + b1);
            if (MODE == 1) {
                int sq = col0 / CDIM;
                int rem = col0 - sq * CDIM;
                int h = rem >> 6, dd = rem & 63;
                float* dst = (sq == 0) ? g_Q : (sq == 1) ? g_K : g_V;
                int bb = row0 >> 10, nn = row0 & 1023;
                size_t base = ((((size_t)bb * NH + h) << 10) + (size_t)nn) * HD + dd;
                *(float2*)(dst + base) = v0;
                *(float2*)(dst + base + 8 * HD) = v1;   // row0+8, same (b,h,d)
            } else {
                float* p = Cout + (size_t)row0 * Ncol + col0;
                *(float2*)p = v0;
                *(float2*)(p + 8 * (size_t)Ncol) = v1;
            }
        }
    }
}

// ---------------------------------------------------------------------------
// Flash attention (fp32 SIMT, diag-masked, per-head temperature).
// Epilogue writes AO as bf16 hi/lo split for the proj GEMM.
// ---------------------------------------------------------------------------
#define Q_PITCH 132
#define K_PITCH 68
#define ATTN_SMEM_FLOATS (64 * Q_PITCH + 64 * K_PITCH + 64 * K_PITCH + 128 * K_PITCH)
#define ATTN_SMEM_BYTES  (ATTN_SMEM_FLOATS * 4)

__global__ void __launch_bounds__(256, 1) attn_kernel(const float* __restrict__ temp)
{
    extern __shared__ float sm[];
    float* Qs = sm;
    float* Ks = sm + 64 * Q_PITCH;
    float* Vs = Ks + 64 * K_PITCH;
    float* Ps = Vs + 64 * K_PITCH;

    const int tid = threadIdx.x;
    const int ty = tid >> 4;
    const int tx = tid & 15;
    const int bh = blockIdx.y;
    const int q0 = blockIdx.x * 128;

    const float* Qg = g_Q + (size_t)bh * NSEQ * HD;
    const float* Kg = g_K + (size_t)bh * NSEQ * HD;
    const float* Vg = g_V + (size_t)bh * NSEQ * HD;
    const float tscale = temp[bh % NH];

#pragma unroll
    for (int it = 0; it < 8; it++) {
        int lin = tid + it * 256;
        int r = lin >> 4;
        int c4 = (lin & 15) << 2;
        float4 v = *(const float4*)&Qg[(size_t)(q0 + r) * HD + c4];
        Qs[(c4 + 0) * Q_PITCH + r] = v.x * tscale;
        Qs[(c4 + 1) * Q_PITCH + r] = v.y * tscale;
        Qs[(c4 + 2) * Q_PITCH + r] = v.z * tscale;
        Qs[(c4 + 3) * Q_PITCH + r] = v.w * tscale;
    }

    u64 Oa[8][2];
    float mrow[8], lrow[8];
#pragma unroll
    for (int i = 0; i < 8; i++) {
        Oa[i][0] = 0ull; Oa[i][1] = 0ull;
        mrow[i] = -1e30f; lrow[i] = 0.0f;
    }

    for (int kt = 0; kt < NSEQ / 64; kt++) {
        const int k0 = kt * 64;
        __syncthreads();
#pragma unroll
        for (int it = 0; it < 4; it++) {
            int lin = tid + it * 256;
            int r = lin >> 4;
            int c4 = (lin & 15) << 2;
            float4 kv = *(const float4*)&Kg[(size_t)(k0 + r) * HD + c4];
            Ks[(c4 + 0) * K_PITCH + r] = kv.x;
            Ks[(c4 + 1) * K_PITCH + r] = kv.y;
            Ks[(c4 + 2) * K_PITCH + r] = kv.z;
            Ks[(c4 + 3) * K_PITCH + r] = kv.w;
            float4 vv = *(const float4*)&Vg[(size_t)(k0 + r) * HD + c4];
            *(float4*)&Vs[r * K_PITCH + c4] = vv;
        }
        __syncthreads();

        u64 sc[8][2];
#pragma unroll
        for (int i = 0; i < 8; i++) { sc[i][0] = 0ull; sc[i][1] = 0ull; }

#pragma unroll 8
        for (int dd = 0; dd < HD; dd++) {
            ulonglong2 kk = *(const ulonglong2*)&Ks[dd * K_PITCH + tx * 4];
            float4 qa = *(const float4*)&Qs[dd * Q_PITCH + ty * 8];
            float4 qb = *(const float4*)&Qs[dd * Q_PITCH + ty * 8 + 4];
            float qv[8] = {qa.x, qa.y, qa.z, qa.w, qb.x, qb.y, qb.z, qb.w};
#pragma unroll
            for (int i = 0; i < 8; i++) {
                u64 qd = pk2(qv[i], qv[i]);
                sc[i][0] = ffma2(qd, kk.x, sc[i][0]);
                sc[i][1] = ffma2(qd, kk.y, sc[i][1]);
            }
        }

#pragma unroll
        for (int i = 0; i < 8; i++) {
            float s0, s1, s2, s3;
            upk2(sc[i][0], s0, s1);
            upk2(sc[i][1], s2, s3);
            int qg = q0 + ty * 8 + i;
            int kg = k0 + tx * 4;
            if (qg == kg)     s0 = -1e30f;
            if (qg == kg + 1) s1 = -1e30f;
            if (qg == kg + 2) s2 = -1e30f;
            if (qg == kg + 3) s3 = -1e30f;

            float mx = fmaxf(fmaxf(s0, s1), fmaxf(s2, s3));
            mx = fmaxf(mx, __shfl_xor_sync(0xffffffffu, mx, 1));
            mx = fmaxf(mx, __shfl_xor_sync(0xffffffffu, mx, 2));
            mx = fmaxf(mx, __shfl_xor_sync(0xffffffffu, mx, 4));
            mx = fmaxf(mx, __shfl_xor_sync(0xffffffffu, mx, 8));

            float mnew = fmaxf(mrow[i], mx);
            float corr = __expf(mrow[i] - mnew);
            mrow[i] = mnew;

            float p0 = __expf(s0 - mnew);
            float p1 = __expf(s1 - mnew);
            float p2 = __expf(s2 - mnew);
            float p3 = __expf(s3 - mnew);
            float rs = (p0 + p1) + (p2 + p3);
            rs += __shfl_xor_sync(0xffffffffu, rs, 1);
            rs += __shfl_xor_sync(0xffffffffu, rs, 2);
            rs += __shfl_xor_sync(0xffffffffu, rs, 4);
            rs += __shfl_xor_sync(0xffffffffu, rs, 8);
            lrow[i] = lrow[i] * corr + rs;

            u64 cd = pk2(corr, corr);
            Oa[i][0] = fmul2(Oa[i][0], cd);
            Oa[i][1] = fmul2(Oa[i][1], cd);

            float4 pv = make_float4(p0, p1, p2, p3);
            *(float4*)&Ps[(ty * 8 + i) * K_PITCH + tx * 4] = pv;
        }
        __syncthreads();

#pragma unroll 2
        for (int c4 = 0; c4 < 16; c4++) {
            ulonglong2 v0 = *(const ulonglong2*)&Vs[(c4 * 4 + 0) * K_PITCH + tx * 4];
            ulonglong2 v1 = *(const ulonglong2*)&Vs[(c4 * 4 + 1) * K_PITCH + tx * 4];
            ulonglong2 v2 = *(const ulonglong2*)&Vs[(c4 * 4 + 2) * K_PITCH + tx * 4];
            ulonglong2 v3 = *(const ulonglong2*)&Vs[(c4 * 4 + 3) * K_PITCH + tx * 4];
#pragma unroll
            for (int i = 0; i < 8; i++) {
                float4 pv = *(const float4*)&Ps[(ty * 8 + i) * K_PITCH + c4 * 4];
                u64 d0 = pk2(pv.x, pv.x);
                Oa[i][0] = ffma2(d0, v0.x, Oa[i][0]);
                Oa[i][1] = ffma2(d0, v0.y, Oa[i][1]);
                u64 d1 = pk2(pv.y, pv.y);
                Oa[i][0] = ffma2(d1, v1.x, Oa[i][0]);
                Oa[i][1] = ffma2(d1, v1.y, Oa[i][1]);
                u64 d2 = pk2(pv.z, pv.z);
                Oa[i][0] = ffma2(d2, v2.x, Oa[i][0]);
                Oa[i][1] = ffma2(d2, v2.y, Oa[i][1]);
                u64 d3 = pk2(pv.w, pv.w);
                Oa[i][0] = ffma2(d3, v3.x, Oa[i][0]);
                Oa[i][1] = ffma2(d3, v3.y, Oa[i][1]);
            }
        }
    }

    // epilogue: AO split to bf16 hi/lo, (B,N,C) layout
    const int b = bh / NH, h = bh % NH;
#pragma unroll
    for (int i = 0; i < 8; i++) {
        float inv = 1.0f / lrow[i];
        float o0, o1, o2, o3;
        upk2(Oa[i][0], o0, o1);
        upk2(Oa[i][1], o2, o3);
        o0 *= inv; o1 *= inv; o2 *= inv; o3 *= inv;
        int n = q0 + ty * 8 + i;
        size_t off = ((size_t)(b * NSEQ + n)) * CDIM + h * HD + tx * 4;
        float4 v = make_float4(o0, o1, o2, o3);
        uint2 hi, lo;
        split4(v, hi, lo);
        *(uint2*)(g_AOh + off) = hi;
        *(uint2*)(g_AOl + off) = lo;
    }
}

// ---------------------------------------------------------------------------
extern "C" void kernel_launch(void* const* d_in, const int* in_sizes, int n_in,
                              void* d_out, int out_size)
{
    (void)in_sizes; (void)n_in; (void)out_size;
    const float* x      = (const float*)d_in[0];
    const float* w_qkv  = (const float*)d_in[1];
    const float* b_qkv  = (const float*)d_in[2];
    const float* w_proj = (const float*)d_in[3];
    const float* b_proj = (const float*)d_in[4];
    const float* temp   = (const float*)d_in[5];
    float* out = (float*)d_out;

    cudaFuncSetAttribute(gemm_mma<1>, cudaFuncAttributeMaxDynamicSharedMemorySize, GEMM_SMEM);
    cudaFuncSetAttribute(gemm_mma<2>, cudaFuncAttributeMaxDynamicSharedMemorySize, GEMM_SMEM);
    cudaFuncSetAttribute(attn_kernel, cudaFuncAttributeMaxDynamicSharedMemorySize, ATTN_SMEM_BYTES);

    __nv_bfloat16 *xh, *xl, *wqh, *wql, *wph, *wpl, *aoh, *aol;
    cudaGetSymbolAddress((void**)&xh,  g_xh);
    cudaGetSymbolAddress((void**)&xl,  g_xl);
    cudaGetSymbolAddress((void**)&wqh, g_wqh);
    cudaGetSymbolAddress((void**)&wql, g_wql);
    cudaGetSymbolAddress((void**)&wph, g_wph);
    cudaGetSymbolAddress((void**)&wpl, g_wpl);
    cudaGetSymbolAddress((void**)&aoh, g_AOh);
    cudaGetSymbolAddress((void**)&aol, g_AOl);

    // prep: split x, transpose+split weights
    split_x_kernel<<<(MROWS * CDIM / 4 + 255) / 256, 256>>>(x, xh, xl, MROWS * CDIM);
    tsplit_w_kernel<<<(192 * 3 * CDIM + 255) / 256, 256>>>(w_qkv, wqh, wql, CDIM, 3 * CDIM);
    tsplit_w_kernel<<<(192 * CDIM + 255) / 256, 256>>>(w_proj, wph, wpl, CDIM, CDIM);

    // QKV GEMM (tensor) with scatter epilogue
    gemm_mma<1><<<dim3(3 * CDIM / 128, MROWS / 128), 256, GEMM_SMEM>>>(
        xh, xl, wqh, wql, b_qkv, nullptr, 3 * CDIM);

    // flash attention (fp32 SIMT)
    attn_kernel<<<dim3(NSEQ / 128, BATCH * NH), 256, ATTN_SMEM_BYTES>>>(temp);

    // output projection (tensor)
    gemm_mma<2><<<dim3(CDIM / 128, MROWS / 128), 256, GEMM_SMEM>>>(
        aoh, aol, wph, wpl, b_proj, out, CDIM);
}

// round 5
// speedup vs baseline: 2.2792x; 1.6603x over previous
#include <cuda_runtime.h>
#include <cuda_bf16.h>
#include <cstdint>

// ---------------------------------------------------------------------------
// Attention_11519102287955 : B=8, N=1024, C=768, H=12, D=64
// Round 5: everything on mma.sync bf16 split hi/lo x3.
//  - QKV GEMM epilogue emits Q(pre-scaled by temp)/K bf16 hi/lo (b,h,n,d) and
//    V transposed bf16 hi/lo (b,h,d,n).
//  - flash attention with mma.sync: S = Qhi.Khi + Qlo.Khi + Qhi.Klo,
//    P reused from S accumulator fragments, O = Phi.Vhi + Plo.Vhi + Phi.Vlo.
//  - GEMMs at 2 CTAs/SM (launch_bounds(256,2)).
// ---------------------------------------------------------------------------

typedef unsigned long long u64;

#define BATCH 8
#define NSEQ  1024
#define CDIM  768
#define NH    12
#define HD    64
#define MROWS (BATCH * NSEQ)   // 8192

// ---- device-global scratch --------------------------------------------------
__device__ __align__(16) __nv_bfloat16 g_Qh[BATCH * NH * NSEQ * HD];
__device__ __align__(16) __nv_bfloat16 g_Ql[BATCH * NH * NSEQ * HD];
__device__ __align__(16) __nv_bfloat16 g_Kh[BATCH * NH * NSEQ * HD];
__device__ __align__(16) __nv_bfloat16 g_Kl[BATCH * NH * NSEQ * HD];
__device__ __align__(16) __nv_bfloat16 g_Vth[BATCH * NH * HD * NSEQ];
__device__ __align__(16) __nv_bfloat16 g_Vtl[BATCH * NH * HD * NSEQ];
__device__ __align__(16) __nv_bfloat16 g_xh[MROWS * CDIM];
__device__ __align__(16) __nv_bfloat16 g_xl[MROWS * CDIM];
__device__ __align__(16) __nv_bfloat16 g_wqh[3 * CDIM * CDIM];
__device__ __align__(16) __nv_bfloat16 g_wql[3 * CDIM * CDIM];
__device__ __align__(16) __nv_bfloat16 g_wph[CDIM * CDIM];
__device__ __align__(16) __nv_bfloat16 g_wpl[CDIM * CDIM];
__device__ __align__(16) __nv_bfloat16 g_AOh[MROWS * CDIM];
__device__ __align__(16) __nv_bfloat16 g_AOl[MROWS * CDIM];

// ---- helpers ----------------------------------------------------------------
__device__ __forceinline__ uint32_t smem_u32(const void* p) {
    uint32_t a;
    asm("{ .reg .u64 t; cvta.to.shared.u64 t, %1; cvt.u32.u64 %0, t; }"
        : "=r"(a) : "l"(p));
    return a;
}

__device__ __forceinline__ void ldsm_x4(uint32_t& r0, uint32_t& r1,
                                        uint32_t& r2, uint32_t& r3, uint32_t a) {
    asm volatile("ldmatrix.sync.aligned.m8n8.x4.shared.b16 {%0,%1,%2,%3}, [%4];"
                 : "=r"(r0), "=r"(r1), "=r"(r2), "=r"(r3) : "r"(a));
}

__device__ __forceinline__ void mma16816(float* d, const uint32_t* a,
                                         const uint32_t* b) {
    asm volatile(
        "mma.sync.aligned.m16n8k16.row.col.f32.bf16.bf16.f32 "
        "{%0,%1,%2,%3}, {%4,%5,%6,%7}, {%8,%9}, {%0,%1,%2,%3};"
        : "+f"(d[0]), "+f"(d[1]), "+f"(d[2]), "+f"(d[3])
        : "r"(a[0]), "r"(a[1]), "r"(a[2]), "r"(a[3]), "r"(b[0]), "r"(b[1]));
}

#define CP_ASYNC16(s, g) \
    asm volatile("cp.async.cg.shared.global [%0], [%1], 16;" :: "r"(s), "l"(g))
#define CP_COMMIT()   asm volatile("cp.async.commit_group;" ::: "memory")
#define CP_WAIT(n)    asm volatile("cp.async.wait_group %0;" :: "n"(n) : "memory")

// split two floats into packed bf16x2 hi + lo residue
__device__ __forceinline__ void split2(float x, float y, uint32_t& hi, uint32_t& lo) {
    __nv_bfloat16 hx = __float2bfloat16(x), hy = __float2bfloat16(y);
    __nv_bfloat16 lx = __float2bfloat16(x - __bfloat162float(hx));
    __nv_bfloat16 ly = __float2bfloat16(y - __bfloat162float(hy));
    hi = ((uint32_t)__bfloat16_as_ushort(hy) << 16) | __bfloat16_as_ushort(hx);
    lo = ((uint32_t)__bfloat16_as_ushort(ly) << 16) | __bfloat16_as_ushort(lx);
}

__device__ __forceinline__ void split4(const float4 v, uint2& hi, uint2& lo) {
    uint32_t h0, l0, h1, l1;
    split2(v.x, v.y, h0, l0);
    split2(v.z, v.w, h1, l1);
    hi.x = h0; hi.y = h1;
    lo.x = l0; lo.y = l1;
}

// ---------------------------------------------------------------------------
// prep kernels: split fp32 -> bf16 hi/lo (x), transpose+split (weights)
// ---------------------------------------------------------------------------
__global__ void __launch_bounds__(256) split_x_kernel(
    const float* __restrict__ x, __nv_bfloat16* __restrict__ xh,
    __nv_bfloat16* __restrict__ xl, int n)
{
    int i = (blockIdx.x * 256 + threadIdx.x) * 4;
    if (i >= n) return;
    float4 v = *(const float4*)(x + i);
    uint2 hi, lo;
    split4(v, hi, lo);
    *(uint2*)(xh + i) = hi;
    *(uint2*)(xl + i) = lo;
}

__global__ void __launch_bounds__(256) tsplit_w_kernel(
    const float* __restrict__ w, __nv_bfloat16* __restrict__ wTh,
    __nv_bfloat16* __restrict__ wTl, int Kd, int Nc)
{
    int u = blockIdx.x * 256 + threadIdx.x;
    int kq = Kd >> 2;
    if (u >= kq * Nc) return;
    int n = u / kq;
    int k0 = (u - n * kq) * 4;
    float4 v;
    v.x = w[(size_t)(k0 + 0) * Nc + n];
    v.y = w[(size_t)(k0 + 1) * Nc + n];
    v.z = w[(size_t)(k0 + 2) * Nc + n];
    v.w = w[(size_t)(k0 + 3) * Nc + n];
    uint2 hi, lo;
    split4(v, hi, lo);
    *(uint2*)(wTh + (size_t)n * Kd + k0) = hi;
    *(uint2*)(wTl + (size_t)n * Kd + k0) = lo;
}

// ---------------------------------------------------------------------------
// mma.sync GEMM: C[8192, Ncol] = A[8192,768] @ B^T (+bias)
// 128x128 CTA tile, 8 warps (64m x 32n), Kc=32, 2-stage cp.async, 2 CTA/SM.
// MODE 1: scatter into g_Qh/l (temp-scaled), g_Kh/l, g_Vth/l (transposed).
// MODE 2: plain fp32 out.
// ---------------------------------------------------------------------------
#define KC 32
#define NCH (CDIM / KC)          // 24
#define PITCH 40                 // bf16 elems per smem row (80 B)
#define MAT_BYTES (128 * PITCH * 2)       // 10240
#define STG_BYTES (4 * MAT_BYTES)         // 40960
#define GEMM_SMEM (2 * STG_BYTES)         // 81920

template <int MODE>
__global__ void __launch_bounds__(256, 2) gemm_mma(
    const __nv_bfloat16* __restrict__ Ah_g, const __nv_bfloat16* __restrict__ Al_g,
    const __nv_bfloat16* __restrict__ Bh_g, const __nv_bfloat16* __restrict__ Bl_g,
    const float* __restrict__ bias, float* __restrict__ Cout, int Ncol,
    const float* __restrict__ temp)
{
    extern __shared__ char smem[];
    const uint32_t sb = smem_u32(smem);

    const int tid = threadIdx.x;
    const int wid = tid >> 5, lane = tid & 31;
    const int wm = wid & 1;
    const int wn = wid >> 1;
    const int bm = blockIdx.y * 128;
    const int bn = blockIdx.x * 128;

    const __nv_bfloat16* gsrc[4] = {Ah_g, Al_g, Bh_g, Bl_g};

    float acc[4][4][4];
#pragma unroll
    for (int i = 0; i < 4; i++)
#pragma unroll
        for (int j = 0; j < 4; j++)
#pragma unroll
            for (int r = 0; r < 4; r++) acc[i][j][r] = 0.0f;

    auto load_stage = [&](int s, int chunk) {
        const int kt = chunk * KC;
        const char* base = smem + s * STG_BYTES;
#pragma unroll
        for (int it = 0; it < 8; it++) {
            int c = tid + it * 256;          // 0..2047
            int mat = c >> 9;
            int r = (c >> 2) & 127;
            int q = c & 3;
            uint32_t saddr = smem_u32(base + mat * MAT_BYTES + r * (PITCH * 2) + q * 16);
            int grow = (mat < 2 ? bm : bn) + r;
            const __nv_bfloat16* g = gsrc[mat] + (size_t)grow * CDIM + kt + q * 8;
            CP_ASYNC16(saddr, g);
        }
    };

    load_stage(0, 0);
    CP_COMMIT();

    for (int i = 0; i < NCH; i++) {
        const int s = i & 1;
        if (i + 1 < NCH) {
            load_stage(s ^ 1, i + 1);
            CP_COMMIT();
            CP_WAIT(1);
        } else {
            CP_WAIT(0);
        }
        __syncthreads();

        const uint32_t ab = sb + s * STG_BYTES;
#pragma unroll
        for (int ks = 0; ks < 2; ks++) {
            uint32_t ah[4][4], al[4][4];
#pragma unroll
            for (int mt = 0; mt < 4; mt++) {
                int row = wm * 64 + mt * 16 + (lane & 15);
                uint32_t off = row * (PITCH * 2) + ks * 32 + (lane >> 4) * 16;
                ldsm_x4(ah[mt][0], ah[mt][1], ah[mt][2], ah[mt][3], ab + off);
                ldsm_x4(al[mt][0], al[mt][1], al[mt][2], al[mt][3],
                        ab + MAT_BYTES + off);
            }
            uint32_t bhf[4][2], blf[4][2];
#pragma unroll
            for (int p = 0; p < 2; p++) {
                int row = wn * 32 + p * 16 + (lane & 15);
                uint32_t off = row * (PITCH * 2) + ks * 32 + (lane >> 4) * 16;
                uint32_t r0, r1, r2, r3;
                ldsm_x4(r0, r1, r2, r3, ab + 2 * MAT_BYTES + off);
                bhf[p * 2 + 0][0] = r0; bhf[p * 2 + 0][1] = r2;
                bhf[p * 2 + 1][0] = r1; bhf[p * 2 + 1][1] = r3;
                ldsm_x4(r0, r1, r2, r3, ab + 3 * MAT_BYTES + off);
                blf[p * 2 + 0][0] = r0; blf[p * 2 + 0][1] = r2;
                blf[p * 2 + 1][0] = r1; blf[p * 2 + 1][1] = r3;
            }
#pragma unroll
            for (int mt = 0; mt < 4; mt++)
#pragma unroll
                for (int nt = 0; nt < 4; nt++) {
                    mma16816(acc[mt][nt], ah[mt], bhf[nt]);
                    mma16816(acc[mt][nt], ah[mt], blf[nt]);
                    mma16816(acc[mt][nt], al[mt], bhf[nt]);
                }
        }
        __syncthreads();
    }

    // ---- epilogue ----
#pragma unroll
    for (int mt = 0; mt < 4; mt++) {
#pragma unroll
        for (int nt = 0; nt < 4; nt++) {
            int row0 = bm + wm * 64 + mt * 16 + (lane >> 2);
            int col0 = bn + wn * 32 + nt * 8 + 2 * (lane & 3);
            float b0 = bias[col0], b1 = bias[col0 + 1];
            float2 v0 = make_float2(acc[mt][nt][0] + b0, acc[mt][nt][1] + b1);
            float2 v1 = make_float2(acc[mt][nt][2] + b0, acc[mt][nt][3] + b1);
            if (MODE == 1) {
                int sq = col0 / CDIM;
                int rem = col0 - sq * CDIM;
                int hh = rem >> 6, dd = rem & 63;
                int bb = row0 >> 10, nn = row0 & 1023;
                if (sq < 2) {
                    float ts = (sq == 0) ? temp[hh] : 1.0f;
                    __nv_bfloat16* dh = sq ? g_Kh : g_Qh;
                    __nv_bfloat16* dl = sq ? g_Kl : g_Ql;
                    size_t base = ((((size_t)bb * NH + hh) << 10) + nn) * HD + dd;
                    uint32_t hi, lo;
                    split2(v0.x * ts, v0.y * ts, hi, lo);
                    *(uint32_t*)(dh + base) = hi;
                    *(uint32_t*)(dl + base) = lo;
                    split2(v1.x * ts, v1.y * ts, hi, lo);
                    *(uint32_t*)(dh + base + 8 * HD) = hi;
                    *(uint32_t*)(dl + base + 8 * HD) = lo;
                } else {
                    // V transposed: (b,h,d,n)
                    size_t vb = (((size_t)bb * NH + hh) * HD + dd) * NSEQ + nn;
                    __nv_bfloat16 t;
                    t = __float2bfloat16(v0.x);
                    g_Vth[vb] = t;
                    g_Vtl[vb] = __float2bfloat16(v0.x - __bfloat162float(t));
                    t = __float2bfloat16(v0.y);
                    g_Vth[vb + NSEQ] = t;
                    g_Vtl[vb + NSEQ] = __float2bfloat16(v0.y - __bfloat162float(t));
                    t = __float2bfloat16(v1.x);
                    g_Vth[vb + 8] = t;
                    g_Vtl[vb + 8] = __float2bfloat16(v1.x - __bfloat162float(t));
                    t = __float2bfloat16(v1.y);
                    g_Vth[vb + NSEQ + 8] = t;
                    g_Vtl[vb + NSEQ + 8] = __float2bfloat16(v1.y - __bfloat162float(t));
                }
            } else {
                float* p = Cout + (size_t)row0 * Ncol + col0;
                *(float2*)p = v0;
                *(float2*)(p + 8 * (size_t)Ncol) = v1;
            }
        }
    }
}

// ---------------------------------------------------------------------------
// Flash attention on mma.sync. One CTA = 128 q-rows of one (b,h); 8 warps,
// warp w owns q rows [w*16, w*16+16). K-tile 128, double-buffered cp.async.
// smem: Q hi/lo (pitch 72 bf16), per-stage K hi/lo (pitch 72) + Vt hi/lo
// (64 rows x pitch 136).
// ---------------------------------------------------------------------------
#define AQ_PITCHB 144
#define AV_PITCHB 272
#define SQH_OFF 0
#define SQL_OFF 18432
#define SK_BASE 36864
#define AKH_OFF 0
#define AKL_OFF 18432
#define AVH_OFF 36864
#define AVL_OFF 54272
#define KSTG_BYTES 71680
#define ATTN_SMEM (36864 + 2 * KSTG_BYTES)   // 180224

__global__ void __launch_bounds__(256, 1) attn_mma()
{
    extern __shared__ char sm[];
    const uint32_t sb = smem_u32(sm);
    const int tid = threadIdx.x;
    const int w = tid >> 5, lane = tid & 31;
    const int bh = blockIdx.y;
    const int q0 = blockIdx.x * 128;
    const int b = bh / NH, h = bh % NH;

    const __nv_bfloat16* Qh = g_Qh + (size_t)bh * NSEQ * HD;
    const __nv_bfloat16* Ql = g_Ql + (size_t)bh * NSEQ * HD;
    const __nv_bfloat16* Kh = g_Kh + (size_t)bh * NSEQ * HD;
    const __nv_bfloat16* Kl = g_Kl + (size_t)bh * NSEQ * HD;
    const __nv_bfloat16* Vth = g_Vth + (size_t)bh * HD * NSEQ;
    const __nv_bfloat16* Vtl = g_Vtl + (size_t)bh * HD * NSEQ;

    // Q tile (hi/lo), pitch 144 B
#pragma unroll
    for (int it = 0; it < 4; it++) {
        int c = tid + it * 256;              // 0..1023
        int row = c >> 3, q = c & 7;
        uint32_t so = sb + row * AQ_PITCHB + q * 16;
        size_t go = (size_t)(q0 + row) * HD + q * 8;
        CP_ASYNC16(so + SQH_OFF, Qh + go);
        CP_ASYNC16(so + SQL_OFF, Ql + go);
    }
    CP_COMMIT();

    auto load_kv = [&](int s, int kt) {
        const uint32_t base = sb + SK_BASE + s * KSTG_BYTES;
        const int k0 = kt * 128;
#pragma unroll
        for (int it = 0; it < 4; it++) {
            int c = tid + it * 256;
            int row = c >> 3, q = c & 7;
            uint32_t so = base + row * AQ_PITCHB + q * 16;
            size_t go = (size_t)(k0 + row) * HD + q * 8;
            CP_ASYNC16(so + AKH_OFF, Kh + go);
            CP_ASYNC16(so + AKL_OFF, Kl + go);
        }
#pragma unroll
        for (int it = 0; it < 4; it++) {
            int c = tid + it * 256;
            int row = c >> 4, q = c & 15;    // 64 rows x 16 chunks
            uint32_t so = base + row * AV_PITCHB + q * 16;
            size_t go = (size_t)row * NSEQ + k0 + q * 8;
            CP_ASYNC16(so + AVH_OFF, Vth + go);
            CP_ASYNC16(so + AVL_OFF, Vtl + go);
        }
    };
    load_kv(0, 0);
    CP_COMMIT();

    uint32_t qfh[4][4], qfl[4][4];
    float oacc[8][4];
#pragma unroll
    for (int j = 0; j < 8; j++)
#pragma unroll
        for (int r = 0; r < 4; r++) oacc[j][r] = 0.0f;
    float m0 = -1e30f, m1 = -1e30f, l0 = 0.0f, l1 = 0.0f;

    for (int kt = 0; kt < NSEQ / 128; kt++) {
        if (kt + 1 < NSEQ / 128) {
            load_kv((kt + 1) & 1, kt + 1);
            CP_COMMIT();
            CP_WAIT(1);
        } else {
            CP_WAIT(0);
        }
        __syncthreads();

        if (kt == 0) {
#pragma unroll
            for (int ks = 0; ks < 4; ks++) {
                int row = w * 16 + (lane & 15);
                uint32_t off = sb + row * AQ_PITCHB + ks * 32 + (lane >> 4) * 16;
                ldsm_x4(qfh[ks][0], qfh[ks][1], qfh[ks][2], qfh[ks][3], off + SQH_OFF);
                ldsm_x4(qfl[ks][0], qfl[ks][1], qfl[ks][2], qfl[ks][3], off + SQL_OFF);
            }
        }

        const uint32_t kb = sb + SK_BASE + (kt & 1) * KSTG_BYTES;
        const int k0 = kt * 128;

        // ---- S = Q.K^T (16 q-rows x 128 kv-cols per warp) ----
        float sacc[16][4];
#pragma unroll
        for (int j = 0; j < 16; j++)
#pragma unroll
            for (int r = 0; r < 4; r++) sacc[j][r] = 0.0f;

#pragma unroll
        for (int ks = 0; ks < 4; ks++) {
#pragma unroll
            for (int p = 0; p < 8; p++) {
                int row = p * 16 + (lane & 15);
                uint32_t off = kb + row * AQ_PITCHB + ks * 32 + (lane >> 4) * 16;
                uint32_t r0, r1, r2, r3, s0, s1, s2, s3;
                ldsm_x4(r0, r1, r2, r3, off + AKH_OFF);
                ldsm_x4(s0, s1, s2, s3, off + AKL_OFF);
                uint32_t bh0[2] = {r0, r2}, bh1[2] = {r1, r3};
                uint32_t bl0[2] = {s0, s2}, bl1[2] = {s1, s3};
                mma16816(sacc[2 * p],     qfh[ks], bh0);
                mma16816(sacc[2 * p],     qfl[ks], bh0);
                mma16816(sacc[2 * p],     qfh[ks], bl0);
                mma16816(sacc[2 * p + 1], qfh[ks], bh1);
                mma16816(sacc[2 * p + 1], qfl[ks], bh1);
                mma16816(sacc[2 * p + 1], qfh[ks], bl1);
            }
        }

        // ---- diag mask + online softmax ----
        const int r0g = q0 + w * 16 + (lane >> 2);
        const int r1g = r0g + 8;
        float mx0 = -1e30f, mx1 = -1e30f;
#pragma unroll
        for (int j = 0; j < 16; j++) {
            int cg = k0 + j * 8 + ((lane & 3) << 1);
            if (r0g == cg)     sacc[j][0] = -1e30f;
            if (r0g == cg + 1) sacc[j][1] = -1e30f;
            if (r1g == cg)     sacc[j][2] = -1e30f;
            if (r1g == cg + 1) sacc[j][3] = -1e30f;
            mx0 = fmaxf(mx0, fmaxf(sacc[j][0], sacc[j][1]));
            mx1 = fmaxf(mx1, fmaxf(sacc[j][2], sacc[j][3]));
        }
        mx0 = fmaxf(mx0, __shfl_xor_sync(0xffffffffu, mx0, 1));
        mx0 = fmaxf(mx0, __shfl_xor_sync(0xffffffffu, mx0, 2));
        mx1 = fmaxf(mx1, __shfl_xor_sync(0xffffffffu, mx1, 1));
        mx1 = fmaxf(mx1, __shfl_xor_sync(0xffffffffu, mx1, 2));

        float mn0 = fmaxf(m0, mx0), mn1 = fmaxf(m1, mx1);
        float cr0 = __expf(m0 - mn0), cr1 = __expf(m1 - mn1);
        m0 = mn0; m1 = mn1;

        float rs0 = 0.0f, rs1 = 0.0f;
        uint32_t pah[8][4], pal[8][4];
#pragma unroll
        for (int j = 0; j < 16; j++) {
            float p0 = __expf(sacc[j][0] - m0);
            float p1 = __expf(sacc[j][1] - m0);
            float p2 = __expf(sacc[j][2] - m1);
            float p3 = __expf(sacc[j][3] - m1);
            rs0 += p0 + p1;
            rs1 += p2 + p3;
            int t = j >> 1, i0 = (j & 1) * 2;
            split2(p0, p1, pah[t][i0], pal[t][i0]);
            split2(p2, p3, pah[t][i0 + 1], pal[t][i0 + 1]);
        }
        rs0 += __shfl_xor_sync(0xffffffffu, rs0, 1);
        rs0 += __shfl_xor_sync(0xffffffffu, rs0, 2);
        rs1 += __shfl_xor_sync(0xffffffffu, rs1, 1);
        rs1 += __shfl_xor_sync(0xffffffffu, rs1, 2);
        l0 = l0 * cr0 + rs0;
        l1 = l1 * cr1 + rs1;

#pragma unroll
        for (int j = 0; j < 8; j++) {
            oacc[j][0] *= cr0; oacc[j][1] *= cr0;
            oacc[j][2] *= cr1; oacc[j][3] *= cr1;
        }

        // ---- O += P.V  (B = V^T [d][kv], K-major) ----
#pragma unroll
        for (int t = 0; t < 8; t++) {
#pragma unroll
            for (int p = 0; p < 4; p++) {
                int row = p * 16 + (lane & 15);
                uint32_t off = kb + AVH_OFF + row * AV_PITCHB + t * 32 + (lane >> 4) * 16;
                uint32_t r0, r1, r2, r3, s0, s1, s2, s3;
                ldsm_x4(r0, r1, r2, r3, off);
                ldsm_x4(s0, s1, s2, s3, off + (AVL_OFF - AVH_OFF));
                uint32_t vh0[2] = {r0, r2}, vh1[2] = {r1, r3};
                uint32_t vl0[2] = {s0, s2}, vl1[2] = {s1, s3};
                mma16816(oacc[2 * p],     pah[t], vh0);
                mma16816(oacc[2 * p],     pal[t], vh0);
                mma16816(oacc[2 * p],     pah[t], vl0);
                mma16816(oacc[2 * p + 1], pah[t], vh1);
                mma16816(oacc[2 * p + 1], pal[t], vh1);
                mma16816(oacc[2 * p + 1], pah[t], vl1);
            }
        }
        __syncthreads();
    }

    // ---- epilogue: AO = O / l, split bf16 hi/lo, (B,N,C) layout ----
    const float inv0 = 1.0f / l0, inv1 = 1.0f / l1;
    const int n0 = q0 + w * 16 + (lane >> 2);
#pragma unroll
    for (int j = 0; j < 8; j++) {
        int c = j * 8 + ((lane & 3) << 1);
        size_t off0 = ((size_t)(b * NSEQ + n0)) * CDIM + h * HD + c;
        uint32_t hi, lo;
        split2(oacc[j][0] * inv0, oacc[j][1] * inv0, hi, lo);
        *(uint32_t*)(g_AOh + off0) = hi;
        *(uint32_t*)(g_AOl + off0) = lo;
        split2(oacc[j][2] * inv1, oacc[j][3] * inv1, hi, lo);
        *(uint32_t*)(g_AOh + off0 + 8 * CDIM) = hi;
        *(uint32_t*)(g_AOl + off0 + 8 * CDIM) = lo;
    }
}

// ---------------------------------------------------------------------------
extern "C" void kernel_launch(void* const* d_in, const int* in_sizes, int n_in,
                              void* d_out, int out_size)
{
    (void)in_sizes; (void)n_in; (void)out_size;
    const float* x      = (const float*)d_in[0];
    const float* w_qkv  = (const float*)d_in[1];
    const float* b_qkv  = (const float*)d_in[2];
    const float* w_proj = (const float*)d_in[3];
    const float* b_proj = (const float*)d_in[4];
    const float* temp   = (const float*)d_in[5];
    float* out = (float*)d_out;

    cudaFuncSetAttribute(gemm_mma<1>, cudaFuncAttributeMaxDynamicSharedMemorySize, GEMM_SMEM);
    cudaFuncSetAttribute(gemm_mma<2>, cudaFuncAttributeMaxDynamicSharedMemorySize, GEMM_SMEM);
    cudaFuncSetAttribute(attn_mma, cudaFuncAttributeMaxDynamicSharedMemorySize, ATTN_SMEM);

    __nv_bfloat16 *xh, *xl, *wqh, *wql, *wph, *wpl, *aoh, *aol;
    cudaGetSymbolAddress((void**)&xh,  g_xh);
    cudaGetSymbolAddress((void**)&xl,  g_xl);
    cudaGetSymbolAddress((void**)&wqh, g_wqh);
    cudaGetSymbolAddress((void**)&wql, g_wql);
    cudaGetSymbolAddress((void**)&wph, g_wph);
    cudaGetSymbolAddress((void**)&wpl, g_wpl);
    cudaGetSymbolAddress((void**)&aoh, g_AOh);
    cudaGetSymbolAddress((void**)&aol, g_AOl);

    // prep: split x, transpose+split weights
    split_x_kernel<<<(MROWS * CDIM / 4 + 255) / 256, 256>>>(x, xh, xl, MROWS * CDIM);
    tsplit_w_kernel<<<(192 * 3 * CDIM + 255) / 256, 256>>>(w_qkv, wqh, wql, CDIM, 3 * CDIM);
    tsplit_w_kernel<<<(192 * CDIM + 255) / 256, 256>>>(w_proj, wph, wpl, CDIM, CDIM);

    // QKV GEMM -> Q(temp-scaled)/K bf16 hi/lo + V^T bf16 hi/lo
    gemm_mma<1><<<dim3(3 * CDIM / 128, MROWS / 128), 256, GEMM_SMEM>>>(
        xh, xl, wqh, wql, b_qkv, nullptr, 3 * CDIM, temp);

    // flash attention (mma.sync)
    attn_mma<<<dim3(NSEQ / 128, BATCH * NH), 256, ATTN_SMEM>>>();

    // output projection
    gemm_mma<2><<<dim3(CDIM / 128, MROWS / 128), 256, GEMM_SMEM>>>(
        aoh, aol, wph, wpl, b_proj, out, CDIM, nullptr);
}